// round 6
// baseline (speedup 1.0000x reference)
#include <cuda_runtime.h>
#include <cuda_bf16.h>
#include <cstdint>
#include <cstddef>

#define HDIM   256
#define WDIM   256
#define C_IN   32
#define KTOT   96
#define WT     64
#define NCHUNK 4
#define SPITCH 68
#define EPITCH 66

// ---- smem byte offsets ------------------------------------------------
#define OFF_AFRAG 0                          // [mt16][kt6][split2][lane32][16B] = 98304
#define OFF_BIAS  98304                      // 256 f32
#define OFF_SCR   99328                      // [96][SPITCH] f32 = 26112
#define OFF_BFRAG 125440                     // [split2][kt6][nt8][lane32][8B] = 24576
#define OFF_IB    150016                     // i gates [64][EPITCH] f32
#define OFF_FB    166912
#define OFF_GB    183808
#define OFF_OS    200704                     // 64 f32 sigma(o) at w=255
#define OFF_HS    200960                     // 64 f32 h column
#define SMEM_BYTES 201216

#define AFRAG_OFF(mt,kt,s,lane) (OFF_AFRAG + ((((mt)*6+(kt))*2+(s))*32 + (lane))*16)
#define BFRAG_OFF(s,kt,nt,lane) (OFF_BFRAG + ((((s)*6+(kt))*8+(nt))*32 + (lane))*8)

typedef unsigned int u32;

// ---- activations (validated: rel_err 4.7e-6 end-to-end in R4) ---------
static __device__ __forceinline__ float sigmoid_f(float x){
    float e = __expf(-x);
    return __fdividef(1.0f, 1.0f + e);
}
static __device__ __forceinline__ float tanh_f(float x){
    return 1.0f - __fdividef(2.0f, __expf(2.0f * x) + 1.0f);
}

static __device__ __forceinline__ void split_bf16(float v, u32& hi, u32& lo){
    __nv_bfloat16 bh = __float2bfloat16(v);
    float r = v - __bfloat162float(bh);
    __nv_bfloat16 bl = __float2bfloat16(r);
    hi = (u32)__bfloat16_as_ushort(bh);
    lo = (u32)__bfloat16_as_ushort(bl);
}
static __device__ __forceinline__ u32 pack2(u32 lo16, u32 hi16){
    return lo16 | (hi16 << 16);
}

static __device__ __forceinline__ void mma16816(float* c, u32 a0, u32 a1, u32 a2, u32 a3,
                                                u32 b0, u32 b1){
    asm volatile("mma.sync.aligned.m16n8k16.row.col.f32.bf16.bf16.f32 "
                 "{%0,%1,%2,%3}, {%4,%5,%6,%7}, {%8,%9}, {%0,%1,%2,%3};"
                 : "+f"(c[0]), "+f"(c[1]), "+f"(c[2]), "+f"(c[3])
                 : "r"(a0), "r"(a1), "r"(a2), "r"(a3), "r"(b0), "r"(b1));
}

// gate reorder: smem oc' order [i,f,g,o]; reference conv order [i,f,o,g]
static __device__ __forceinline__ int orig_oc(int ocp){
    return (ocp < 128) ? ocp : ((ocp < 192) ? (ocp + 64) : (ocp - 64));
}
// k = kh*32 + c  ->  flat W index offset c*3 + kh
static __device__ __forceinline__ int ck_of(int k){ return (k & 31) * 3 + (k >> 5); }

extern __shared__ char smem[];

__global__ void __launch_bounds__(256, 1)
rowlstm_mma(const float* __restrict__ x,
            const float* __restrict__ Wc,
            const float* __restrict__ bc,
            float* __restrict__ out,
            int nrows)
{
    const int tid  = threadIdx.x;
    const int wid  = tid >> 5;
    const int lane = tid & 31;
    const int g    = lane >> 2;
    const int tg   = lane & 3;

    float* bias_s = (float*)(smem + OFF_BIAS);
    float* scr    = (float*)(smem + OFF_SCR);
    float* ib     = (float*)(smem + OFF_IB);
    float* fb     = (float*)(smem + OFF_FB);
    float* gb2    = (float*)(smem + OFF_GB);
    float* o_s    = (float*)(smem + OFF_OS);
    float* h_s    = (float*)(smem + OFF_HS);

    // ================= Phase 0 (once): bias + A fragments (hi/lo bf16) ====
    bias_s[tid] = bc[orig_oc(tid)];
    for (int combo = wid; combo < 96; combo += 8){
        const int mt = combo / 6, kt = combo % 6;
        const int r0 = mt * 16 + g;
        const int k0 = kt * 16 + 2 * tg;
        const int o0 = orig_oc(r0), o1 = orig_oc(r0 + 8);
        float f00 = Wc[o0 * KTOT + ck_of(k0)];
        float f01 = Wc[o0 * KTOT + ck_of(k0 + 1)];
        float f02 = Wc[o0 * KTOT + ck_of(k0 + 8)];
        float f03 = Wc[o0 * KTOT + ck_of(k0 + 9)];
        float f10 = Wc[o1 * KTOT + ck_of(k0)];
        float f11 = Wc[o1 * KTOT + ck_of(k0 + 1)];
        float f12 = Wc[o1 * KTOT + ck_of(k0 + 8)];
        float f13 = Wc[o1 * KTOT + ck_of(k0 + 9)];
        u32 h00,l00,h01,l01,h02,l02,h03,l03,h10,l10,h11,l11,h12,l12,h13,l13;
        split_bf16(f00,h00,l00); split_bf16(f01,h01,l01);
        split_bf16(f02,h02,l02); split_bf16(f03,h03,l03);
        split_bf16(f10,h10,l10); split_bf16(f11,h11,l11);
        split_bf16(f12,h12,l12); split_bf16(f13,h13,l13);
        uint4 hi4 = make_uint4(pack2(h00,h01), pack2(h10,h11), pack2(h02,h03), pack2(h12,h13));
        uint4 lo4 = make_uint4(pack2(l00,l01), pack2(l10,l11), pack2(l02,l03), pack2(l12,l13));
        *(uint4*)(smem + AFRAG_OFF(mt,kt,0,lane)) = hi4;
        *(uint4*)(smem + AFRAG_OFF(mt,kt,1,lane)) = lo4;
    }
    __syncthreads();

    // ================= row loop (persistent CTA) ==========================
    for (int row = blockIdx.x; row < nrows; row += gridDim.x){
        const int h = row & (HDIM - 1);
        const int b = row >> 8;
        float creg = 0.0f;                      // cell state (warps 0,1)

        // stage chunk `chunk` into scr with threads [tbase, tbase+nth)
        auto stage = [&](int chunk, int tbase, int nth){
            const int w0g = chunk * WT;
            const int tl = tid - tbase;
            for (int idx = tl; idx < 1536; idx += nth){   // float4 slots
                int r  = idx >> 4;            // 0..95 (k index)
                int c4 = idx & 15;
                int hh = h + (r >> 5) - 1;
                float4 v = make_float4(0.f, 0.f, 0.f, 0.f);
                if (hh >= 0 && hh < HDIM)
                    v = *(const float4*)(x + (((size_t)b * C_IN + (r & 31)) * HDIM + hh) * WDIM + w0g + c4 * 4);
                *(float4*)(scr + r * SPITCH + c4 * 4) = v;
            }
        };

        stage(0, 0, 256);
        __syncthreads();

        for (int n = 0; n < NCHUNK; n++){
            // ---- build B fragments (hi/lo): nt = wid, kt loop
            {
                const int nt = wid;
                const int w  = nt * 8 + g;
                #pragma unroll
                for (int kt = 0; kt < 6; kt++){
                    const int k0 = kt * 16 + 2 * tg;
                    float v00 = scr[k0 * SPITCH + w];
                    float v01 = scr[(k0 + 1) * SPITCH + w];
                    float v10 = scr[(k0 + 8) * SPITCH + w];
                    float v11 = scr[(k0 + 9) * SPITCH + w];
                    u32 hA,lA,hB,lB,hC,lC,hD,lD;
                    split_bf16(v00,hA,lA); split_bf16(v01,hB,lB);
                    split_bf16(v10,hC,lC); split_bf16(v11,hD,lD);
                    *(uint2*)(smem + BFRAG_OFF(0,kt,nt,lane)) = make_uint2(pack2(hA,hB), pack2(hC,hD));
                    *(uint2*)(smem + BFRAG_OFF(1,kt,nt,lane)) = make_uint2(pack2(lA,lB), pack2(lC,lD));
                }
            }
            __syncthreads();   // S2: Bfrag ready

            // ---- MMA: one unit per warp = 3 mt x 4 nt, register-blocked
            {
                const int t  = wid >> 1;        // mt triple: mt = 3t..3t+2
                const int nh = wid & 1;         // nt = 4nh..4nh+3
                float acc[3][4][4];
                #pragma unroll
                for (int m = 0; m < 3; m++)
                    #pragma unroll
                    for (int q = 0; q < 4; q++)
                        acc[m][q][0]=acc[m][q][1]=acc[m][q][2]=acc[m][q][3]=0.f;

                #pragma unroll
                for (int p = 0; p < 3; p++){    // (Ah,Bh),(Al,Bh),(Ah,Bl)
                    const int as = (p == 1) ? 1 : 0;
                    const int bs = (p == 2) ? 1 : 0;
                    #pragma unroll
                    for (int kt = 0; kt < 6; kt++){
                        uint4 a0 = *(const uint4*)(smem + AFRAG_OFF(3*t+0,kt,as,lane));
                        uint4 a1 = *(const uint4*)(smem + AFRAG_OFF(3*t+1,kt,as,lane));
                        uint4 a2 = *(const uint4*)(smem + AFRAG_OFF(3*t+2,kt,as,lane));
                        #pragma unroll
                        for (int q = 0; q < 4; q++){
                            uint2 bv = *(const uint2*)(smem + BFRAG_OFF(bs,kt,4*nh+q,lane));
                            mma16816(acc[0][q], a0.x, a0.y, a0.z, a0.w, bv.x, bv.y);
                            mma16816(acc[1][q], a1.x, a1.y, a1.z, a1.w, bv.x, bv.y);
                            mma16816(acc[2][q], a2.x, a2.y, a2.z, a2.w, bv.x, bv.y);
                        }
                    }
                }

                // ---- fused epilogue: bias + activation + STS.64
                #pragma unroll
                for (int m = 0; m < 3; m++){
                    const int mt   = 3 * t + m;
                    const int gate = mt >> 2;            // 0=i,1=f,2=g
                    const int hidb = (mt & 3) * 16;
                    const float bg0 = bias_s[mt * 16 + g];
                    const float bg1 = bias_s[mt * 16 + g + 8];
                    float* buf = (gate == 0) ? ib : ((gate == 1) ? fb : gb2);
                    #pragma unroll
                    for (int q = 0; q < 4; q++){
                        const int wq = (4 * nh + q) * 8 + 2 * tg;
                        float a0, a1, a2, a3;
                        if (gate < 2){
                            a0 = sigmoid_f(acc[m][q][0] + bg0); a1 = sigmoid_f(acc[m][q][1] + bg0);
                            a2 = sigmoid_f(acc[m][q][2] + bg1); a3 = sigmoid_f(acc[m][q][3] + bg1);
                        } else {
                            a0 = tanh_f(acc[m][q][0] + bg0); a1 = tanh_f(acc[m][q][1] + bg0);
                            a2 = tanh_f(acc[m][q][2] + bg1); a3 = tanh_f(acc[m][q][3] + bg1);
                        }
                        *(float2*)(buf + (hidb + g    ) * EPITCH + wq) = make_float2(a0, a1);
                        *(float2*)(buf + (hidb + g + 8) * EPITCH + wq) = make_float2(a2, a3);
                    }
                }
            }

            // ---- o gate: last chunk only, w=255 (nt=7), warps 1,3,5,7
            if (n == NCHUNK - 1 && (wid & 1)){
                const int mt = 12 + (wid >> 1);
                float acc[4] = {0.f, 0.f, 0.f, 0.f};
                #pragma unroll
                for (int p = 0; p < 3; p++){
                    const int as = (p == 1) ? 1 : 0;
                    const int bs = (p == 2) ? 1 : 0;
                    #pragma unroll
                    for (int kt = 0; kt < 6; kt++){
                        uint4 av = *(const uint4*)(smem + AFRAG_OFF(mt,kt,as,lane));
                        uint2 bv = *(const uint2*)(smem + BFRAG_OFF(bs,kt,7,lane));
                        mma16816(acc, av.x, av.y, av.z, av.w, bv.x, bv.y);
                    }
                }
                if (tg == 3){   // col 2tg+1 = 7 -> local w 63 = global 255
                    const int oc0 = mt * 16 + g;
                    o_s[oc0 - 192]     = sigmoid_f(acc[1] + bias_s[oc0]);
                    o_s[oc0 - 192 + 8] = sigmoid_f(acc[3] + bias_s[oc0 + 8]);
                }
            }
            __syncthreads();   // S3: gates (+ o_s on last chunk) visible

            // ---- parallel tail: warps 0-1 scan chunk n; warps 2-7 stage n+1
            if (wid < 2){
                const int hid = wid * 32 + lane;
                float c = creg;
                #pragma unroll 8
                for (int w = 0; w < WT; w++){
                    float fv = fb [hid * EPITCH + w];
                    float iv = ib [hid * EPITCH + w];
                    float gv = gb2[hid * EPITCH + w];
                    c = fv * c + iv * gv;
                }
                creg = c;
                if (n == NCHUNK - 1)
                    h_s[hid] = o_s[hid] * tanh_f(c);
            } else if (n < NCHUNK - 1){
                stage(n + 1, 64, 192);
            }
            __syncthreads();   // S1: scr(n+1) ready / h_s ready
        }

        // ---- broadcast write out[b][hid][h][0..255]
        {
            const int hq = tid >> 6;
            const int w4 = tid & 63;
            #pragma unroll
            for (int r = 0; r < 16; r++){
                int hid = hq * 16 + r;
                float v = h_s[hid];
                float4 vv = make_float4(v, v, v, v);
                *(float4*)(out + (((size_t)b * 64 + hid) * HDIM + h) * WDIM + w4 * 4) = vv;
            }
        }
        __syncthreads();
    }
}

extern "C" void kernel_launch(void* const* d_in, const int* in_sizes, int n_in,
                              void* d_out, int out_size)
{
    const float* x  = (const float*)d_in[0];
    const float* Wc = (const float*)d_in[1];
    const float* bc = (const float*)d_in[2];
    float* out = (float*)d_out;

    const int B = in_sizes[0] / (C_IN * HDIM * WDIM);
    const int nrows = B * HDIM;

    static bool attr_done = false;
    if (!attr_done){
        cudaFuncSetAttribute(rowlstm_mma,
                             cudaFuncAttributeMaxDynamicSharedMemorySize,
                             SMEM_BYTES);
        attr_done = true;
    }

    int grid = 148;
    if (nrows < grid) grid = nrows;
    rowlstm_mma<<<grid, 256, SMEM_BYTES>>>(x, Wc, bc, out, nrows);
}